// round 1
// baseline (speedup 1.0000x reference)
#include <cuda_runtime.h>

// Correlation layer: out[b, (dy+4)*9+(dx+4), y, x] =
//   (1/C) * sum_c first[b,c,y,x] * second[b,c,y+dy,x+dx]   (zero-padded)
// Shapes: B=8, C=256, H=96, W=160, MAX_DISP=4 -> 81 displacements.

#define MAXD    4
#define NDISP   9              // 2*MAXD+1
#define BATCH   8
#define CHN     256
#define HH      96
#define WW      160

#define TY      4              // pixel rows per block
#define TX      32             // pixel cols per block
#define PX      4              // pixels per thread (x-strip)
#define CH      8              // channels staged per iteration

#define BROWS   (TY + 2*MAXD)  // 12
#define BCOLS   (TX + 2*MAXD)  // 40
#define ATILE   (TY * TX)      // 128
#define BTILE   (BROWS * BCOLS)// 480
#define NTHREADS 288           // 8 xgroups * 4 rows * 9 dy = 9 warps

__global__ __launch_bounds__(NTHREADS, 2)
void corr_kernel(const float* __restrict__ first,
                 const float* __restrict__ second,
                 float* __restrict__ out)
{
    __shared__ float As[CH * ATILE];   //  4 KB
    __shared__ float Bs[CH * BTILE];   // 15.36 KB

    const int xt = blockIdx.x * TX;    // tile x origin
    const int y0 = blockIdx.y * TY;    // tile y origin
    const int b  = blockIdx.z;

    const int tid = threadIdx.x;
    const int xg  = tid & 7;           // x-group: pixels xt+4*xg .. +3
    const int yy  = (tid >> 3) & 3;    // row within tile
    const int w   = tid >> 5;          // warp id == dy index 0..8 (dy = w-4)

    float acc[PX][NDISP];
    #pragma unroll
    for (int i = 0; i < PX; ++i)
        #pragma unroll
        for (int j = 0; j < NDISP; ++j)
            acc[i][j] = 0.0f;

    const size_t baseF = (size_t)b * CHN * HH * WW;
    const size_t baseS = baseF;

    for (int c0 = 0; c0 < CHN; c0 += CH) {
        __syncthreads();

        // ---- stage B halo tile: CH channels of 12x40 (zero-padded) ----
        for (int i = tid; i < CH * BTILE; i += NTHREADS) {
            int c   = i / BTILE;
            int rem = i - c * BTILE;
            int r   = rem / BCOLS;
            int col = rem - r * BCOLS;
            int gy  = y0 - MAXD + r;
            int gx  = xt - MAXD + col;
            float v = 0.0f;
            if ((unsigned)gy < (unsigned)HH && (unsigned)gx < (unsigned)WW)
                v = second[baseS + ((size_t)(c0 + c) * HH + gy) * WW + gx];
            Bs[i] = v;
        }
        // ---- stage A tile: CH channels of 4x32 (always in-bounds) ----
        for (int i = tid; i < CH * ATILE; i += NTHREADS) {
            int c   = i >> 7;          // / 128
            int rem = i & 127;
            int r   = rem >> 5;
            int col = rem & 31;
            As[i] = first[baseF + ((size_t)(c0 + c) * HH + (y0 + r)) * WW + (xt + col)];
        }
        __syncthreads();

        // ---- accumulate CH channels ----
        #pragma unroll
        for (int cc = 0; cc < CH; ++cc) {
            const float4 av =
                *reinterpret_cast<const float4*>(&As[cc * ATILE + yy * TX + 4 * xg]);
            const float* brow = &Bs[cc * BTILE + (yy + w) * BCOLS + 4 * xg];
            const float4 b0 = *reinterpret_cast<const float4*>(brow);
            const float4 b1 = *reinterpret_cast<const float4*>(brow + 4);
            const float4 b2 = *reinterpret_cast<const float4*>(brow + 8);

            const float a[PX]  = {av.x, av.y, av.z, av.w};
            const float bv[12] = {b0.x, b0.y, b0.z, b0.w,
                                  b1.x, b1.y, b1.z, b1.w,
                                  b2.x, b2.y, b2.z, b2.w};
            #pragma unroll
            for (int i = 0; i < PX; ++i)
                #pragma unroll
                for (int j = 0; j < NDISP; ++j)
                    acc[i][j] = fmaf(a[i], bv[i + j], acc[i][j]);
        }
    }

    // ---- epilogue: mean over C, coalesced float4 stores ----
    const float scale = 1.0f / (float)CHN;
    const int y = y0 + yy;
    const int x = xt + 4 * xg;
    #pragma unroll
    for (int j = 0; j < NDISP; ++j) {
        const int d = w * NDISP + j;
        float4 o;
        o.x = acc[0][j] * scale;
        o.y = acc[1][j] * scale;
        o.z = acc[2][j] * scale;
        o.w = acc[3][j] * scale;
        *reinterpret_cast<float4*>(
            &out[(((size_t)b * 81 + d) * HH + y) * WW + x]) = o;
    }
}

extern "C" void kernel_launch(void* const* d_in, const int* in_sizes, int n_in,
                              void* d_out, int out_size)
{
    const float* first  = (const float*)d_in[0];
    const float* second = (const float*)d_in[1];
    float* out          = (float*)d_out;

    dim3 grid(WW / TX, HH / TY, BATCH);   // (5, 24, 8)
    dim3 block(NTHREADS);
    corr_kernel<<<grid, block>>>(first, second, out);
}

// round 2
// speedup vs baseline: 3.6022x; 3.6022x over previous
#include <cuda_runtime.h>
#include <cstdint>

// Correlation layer: out[b, (dy+4)*9+(dx+4), y, x] =
//   (1/C) * sum_c first[b,c,y,x] * second[b,c,y+dy,x+dx]   (zero-padded)
// B=8, C=256, H=96, W=160, MAX_DISP=4 -> 81 displacements.

#define MAXD    4
#define NDISP   9
#define BATCH   8
#define CHN     256
#define HH      96
#define WW      160
#define HW      (HH*WW)

#define TY      4
#define TX      32
#define PX      4
#define CH      8
#define NITER   (CHN/CH)          // 32

#define BROWS   (TY + 2*MAXD)     // 12
#define BCOLS   (TX + 2*MAXD)     // 40  (10 aligned float4, halo start xt-4 is 16B-aligned)
#define BTILE   (BROWS*BCOLS)     // 480
#define ATILE   (TY*TX)           // 128
#define BUF_FLOATS (CH*(BTILE+ATILE))  // 4864 floats per buffer (19456 B)
#define NTHREADS 288              // 9 warps; warp id == dy index

#define NB4     (CH*BTILE/4)      // 960 B-tile float4 slots
#define NA4     (CH*ATILE/4)      // 256 A-tile float4 slots
#define NTOT4   (NB4+NA4)         // 1216
#define NSLOT   5                 // ceil(1216/288)

__device__ __forceinline__ uint32_t smem_u32(const void* p) {
    return (uint32_t)__cvta_generic_to_shared(p);
}
// 16B async copy, zero-fills when srcsz==0 (used for the fixed OOB halo pattern)
__device__ __forceinline__ void cp16(uint32_t s, const void* g, int srcsz) {
    asm volatile("cp.async.cg.shared.global [%0], [%1], 16, %2;\n"
                 :: "r"(s), "l"(g), "r"(srcsz));
}
__device__ __forceinline__ void cp_commit() {
    asm volatile("cp.async.commit_group;\n" ::: "memory");
}
template<int N>
__device__ __forceinline__ void cp_wait() {
    asm volatile("cp.async.wait_group %0;\n" :: "n"(N) : "memory");
}

__global__ __launch_bounds__(NTHREADS, 2)
void corr_kernel(const float* __restrict__ first,
                 const float* __restrict__ second,
                 float* __restrict__ out)
{
    __shared__ float smem[2 * BUF_FLOATS];   // double buffer, 38912 B

    const int xt  = blockIdx.x * TX;
    const int y0  = blockIdx.y * TY;
    const int b   = blockIdx.z;
    const int tid = threadIdx.x;

    // ---- precompute staging slots (hoisted out of channel loop) ----
    const float* gsrc[NSLOT];
    int          gsz [NSLOT];     // 16 = copy, 0 = zero-fill, -1 = skip
    uint32_t     sdst[NSLOT];     // smem byte address in buffer 0

    const size_t base = (size_t)b * CHN * HW;
    const uint32_t smem0 = smem_u32(smem);

    #pragma unroll
    for (int k = 0; k < NSLOT; ++k) {
        const int s = tid + k * NTHREADS;
        gsz[k]  = -1;
        gsrc[k] = first;
        sdst[k] = smem0;
        if (s < NB4) {
            // B halo tile: CH channels of 12 rows x 10 float4 (40 floats)
            const int c   = s / 120;
            const int rem = s - c * 120;
            const int r   = rem / 10;
            const int q   = rem - r * 10;
            const int gy  = y0 - MAXD + r;
            const int gx  = xt - MAXD + 4 * q;        // multiple of 4 -> float4 all-in or all-out
            const bool ok = ((unsigned)gy < (unsigned)HH) && (gx >= 0) && (gx + 4 <= WW);
            gsz[k]  = ok ? 16 : 0;
            gsrc[k] = ok ? (second + base + ((size_t)c * HH + gy) * WW + gx) : second;
            sdst[k] = smem0 + (uint32_t)(c * BTILE + r * BCOLS + 4 * q) * 4u;
        } else if (s < NTOT4) {
            // A tile: CH channels of 4 rows x 8 float4 (32 floats), always in-bounds
            const int j   = s - NB4;
            const int c   = j >> 5;
            const int rem = j & 31;
            const int r   = rem >> 3;
            const int q   = rem & 7;
            gsz[k]  = 16;
            gsrc[k] = first + base + ((size_t)c * HH + y0 + r) * WW + xt + 4 * q;
            sdst[k] = smem0 + (uint32_t)(CH * BTILE + c * ATILE + r * TX + 4 * q) * 4u;
        }
    }

    const int xg = tid & 7;
    const int yy = (tid >> 3) & 3;
    const int w  = tid >> 5;          // dy index 0..8

    float acc[PX][NDISP];
    #pragma unroll
    for (int i = 0; i < PX; ++i)
        #pragma unroll
        for (int j = 0; j < NDISP; ++j)
            acc[i][j] = 0.0f;

    // ---- prologue: stage chunk 0 into buffer 0 ----
    #pragma unroll
    for (int k = 0; k < NSLOT; ++k)
        if (gsz[k] >= 0) {
            cp16(sdst[k], gsrc[k], gsz[k]);
            gsrc[k] += CH * HW;
        }
    cp_commit();

    int buf = 0;
    #pragma unroll 1
    for (int it = 0; it < NITER; ++it) {
        const uint32_t nbuf_off = (uint32_t)((buf ^ 1) * BUF_FLOATS * 4);
        if (it + 1 < NITER) {
            #pragma unroll
            for (int k = 0; k < NSLOT; ++k)
                if (gsz[k] >= 0) {
                    cp16(sdst[k] + nbuf_off, gsrc[k], gsz[k]);
                    gsrc[k] += CH * HW;
                }
            cp_commit();
            cp_wait<1>();
        } else {
            cp_wait<0>();
        }
        __syncthreads();    // chunk 'it' visible to all threads

        const float* Bb = smem + buf * BUF_FLOATS;
        const float* Ab = Bb + CH * BTILE;
        #pragma unroll
        for (int cc = 0; cc < CH; ++cc) {
            const float4 av =
                *reinterpret_cast<const float4*>(&Ab[cc * ATILE + yy * TX + 4 * xg]);
            const float* brow = &Bb[cc * BTILE + (yy + w) * BCOLS + 4 * xg];
            const float4 b0 = *reinterpret_cast<const float4*>(brow);
            const float4 b1 = *reinterpret_cast<const float4*>(brow + 4);
            const float4 b2 = *reinterpret_cast<const float4*>(brow + 8);

            const float a[PX]  = {av.x, av.y, av.z, av.w};
            const float bv[12] = {b0.x, b0.y, b0.z, b0.w,
                                  b1.x, b1.y, b1.z, b1.w,
                                  b2.x, b2.y, b2.z, b2.w};
            #pragma unroll
            for (int i = 0; i < PX; ++i)
                #pragma unroll
                for (int j = 0; j < NDISP; ++j)
                    acc[i][j] = fmaf(a[i], bv[i + j], acc[i][j]);
        }
        __syncthreads();    // compute done before next overwrite of this buffer
        buf ^= 1;
    }

    // ---- epilogue: mean over C, coalesced float4 stores ----
    const float scale = 1.0f / (float)CHN;
    const int y = y0 + yy;
    const int x = xt + 4 * xg;
    #pragma unroll
    for (int j = 0; j < NDISP; ++j) {
        const int d = w * NDISP + j;
        float4 o;
        o.x = acc[0][j] * scale;
        o.y = acc[1][j] * scale;
        o.z = acc[2][j] * scale;
        o.w = acc[3][j] * scale;
        *reinterpret_cast<float4*>(
            &out[(((size_t)b * 81 + d) * HH + y) * WW + x]) = o;
    }
}

extern "C" void kernel_launch(void* const* d_in, const int* in_sizes, int n_in,
                              void* d_out, int out_size)
{
    const float* first  = (const float*)d_in[0];
    const float* second = (const float*)d_in[1];
    float* out          = (float*)d_out;

    dim3 grid(WW / TX, HH / TY, BATCH);   // (5, 24, 8)
    dim3 block(NTHREADS);
    corr_kernel<<<grid, block>>>(first, second, out);
}